// round 5
// baseline (speedup 1.0000x reference)
#include <cuda_runtime.h>
#include <math.h>

#define D_MODEL 1024
#define NH 16
#define DK 64
#define BATCH 2
#define SEQ 2048
#define M_ROWS (BATCH * SEQ)   // 4096

#define NEG_INF (__int_as_float(0xff800000))

// Scratch (allocation-free rule: __device__ globals)
__device__ float g_Q[M_ROWS * D_MODEL];
__device__ float g_K[M_ROWS * D_MODEL];
__device__ float g_V[M_ROWS * D_MODEL];
__device__ float g_A[M_ROWS * D_MODEL];

// ---------------------------------------------------------------------------
// GEMM: C[M,N] = A[M,K] * W[N,K]^T   (y = x @ W.T), all row-major fp32
// 64x64 tile, BK=16, 16x16 threads, 4x4 micro-tile.
// ---------------------------------------------------------------------------
__global__ void gemm_xwt(const float* __restrict__ A,
                         const float* __restrict__ W,
                         float* __restrict__ C,
                         int M, int N, int K) {
    __shared__ float As[64][17];
    __shared__ float Ws[64][17];

    const int tx = threadIdx.x;      // 0..15
    const int ty = threadIdx.y;      // 0..15
    const int tid = ty * 16 + tx;
    const int m0 = blockIdx.y * 64;
    const int n0 = blockIdx.x * 64;

    float acc[4][4];
#pragma unroll
    for (int i = 0; i < 4; i++)
#pragma unroll
        for (int j = 0; j < 4; j++) acc[i][j] = 0.f;

    for (int k0 = 0; k0 < K; k0 += 16) {
#pragma unroll
        for (int i = tid; i < 64 * 16; i += 256) {
            int rr = i >> 4, cc = i & 15;
            As[rr][cc] = A[(size_t)(m0 + rr) * K + k0 + cc];
            Ws[rr][cc] = W[(size_t)(n0 + rr) * K + k0 + cc];
        }
        __syncthreads();
#pragma unroll
        for (int kk = 0; kk < 16; kk++) {
            float a[4], w[4];
#pragma unroll
            for (int i = 0; i < 4; i++) a[i] = As[ty * 4 + i][kk];
#pragma unroll
            for (int j = 0; j < 4; j++) w[j] = Ws[tx * 4 + j][kk];
#pragma unroll
            for (int i = 0; i < 4; i++)
#pragma unroll
                for (int j = 0; j < 4; j++) acc[i][j] += a[i] * w[j];
        }
        __syncthreads();
    }

#pragma unroll
    for (int i = 0; i < 4; i++)
#pragma unroll
        for (int j = 0; j < 4; j++)
            C[(size_t)(m0 + ty * 4 + i) * N + n0 + tx * 4 + j] = acc[i][j];
}

// ---------------------------------------------------------------------------
// RoPE applied in-place to Q and K. Layout [row=b*S+s][h*64+d].
// Pairs (2i, 2i+1) within each head, freq = theta^(-2i/dk).
// ---------------------------------------------------------------------------
__global__ void rope_kernel(float* __restrict__ Q, float* __restrict__ K) {
    int idx = blockIdx.x * blockDim.x + threadIdx.x;   // over M_ROWS * 512 pairs
    if (idx >= M_ROWS * (D_MODEL / 2)) return;
    int row = idx >> 9;           // /512
    int p   = idx & 511;
    int h = p >> 5;               // /32 pairs-per-head
    int i = p & 31;               // pair index within head
    int s = row & (SEQ - 1);      // row % 2048

    float freq = powf(10000.0f, -((float)(2 * i) / (float)DK));
    float ang = (float)s * freq;
    float c = cosf(ang), sn = sinf(ang);

    size_t off = (size_t)row * D_MODEL + h * DK + 2 * i;
    float q1 = Q[off], q2 = Q[off + 1];
    Q[off]     = q1 * c - q2 * sn;
    Q[off + 1] = q1 * sn + q2 * c;
    float k1 = K[off], k2 = K[off + 1];
    K[off]     = k1 * c - k2 * sn;
    K[off + 1] = k1 * sn + k2 * c;
}

// ---------------------------------------------------------------------------
// Causal flash attention. One CTA per (qtile=64 rows, head, batch).
// 256 threads: thread t handles row r = t/4, output cols qd*16..qd*16+15.
// Dynamic smem: Qt (transposed, 64x64) | KP (64x65, K then reused for P) | V (64x65)
// ---------------------------------------------------------------------------
#define ATTN_SMEM_FLOATS (64 * 64 + 2 * 64 * 65)

__global__ void attn_kernel(const float* __restrict__ Q,
                            const float* __restrict__ K,
                            const float* __restrict__ V,
                            float* __restrict__ O) {
    extern __shared__ float smem[];
    float* Qt = smem;                 // [64][64]  Qt[kk*64 + r]
    float* KP = smem + 64 * 64;       // [64][65]
    float* Vs = KP + 64 * 65;         // [64][65]

    const int qt = blockIdx.x;        // query tile 0..31
    const int h  = blockIdx.y;        // head
    const int b  = blockIdx.z;        // batch
    const int t  = threadIdx.x;       // 0..255
    const int r  = t >> 2;            // 0..63
    const int qd = t & 3;             // 0..3

    const size_t rowbase = (size_t)b * SEQ;
    const float* Qb = Q + (rowbase * D_MODEL) + h * DK;
    const float* Kb = K + (rowbase * D_MODEL) + h * DK;
    const float* Vb = V + (rowbase * D_MODEL) + h * DK;

    const int qrow0 = qt * 64;

    // load Q tile (transposed into smem)
    for (int i = t; i < 64 * 64; i += 256) {
        int rr = i >> 6, cc = i & 63;
        Qt[cc * 64 + rr] = Qb[(size_t)(qrow0 + rr) * D_MODEL + cc];
    }

    float m = NEG_INF;
    float l = 0.f;
    float acc[16];
#pragma unroll
    for (int i = 0; i < 16; i++) acc[i] = 0.f;
    const float scale = 0.125f;       // 1/sqrt(64)

    for (int jt = 0; jt <= qt; jt++) {
        const int krow0 = jt * 64;
        __syncthreads();              // P from prev iter fully consumed
        for (int i = t; i < 64 * 64; i += 256) {
            int rr = i >> 6, cc = i & 63;
            KP[rr * 65 + cc] = Kb[(size_t)(krow0 + rr) * D_MODEL + cc];
            Vs[rr * 65 + cc] = Vb[(size_t)(krow0 + rr) * D_MODEL + cc];
        }
        __syncthreads();

        // scores: 16 columns per thread
        float sreg[16];
        float mloc = NEG_INF;
        const bool diag = (jt == qt);
#pragma unroll
        for (int j = 0; j < 16; j++) {
            int c = qd * 16 + j;
            float a2 = 0.f;
#pragma unroll
            for (int kk = 0; kk < 64; kk++)
                a2 += Qt[kk * 64 + r] * KP[c * 65 + kk];
            a2 *= scale;
            if (diag && c > r) a2 = NEG_INF;
            sreg[j] = a2;
            mloc = fmaxf(mloc, a2);
        }
        // row reduce over the 4 lanes of this row
        mloc = fmaxf(mloc, __shfl_xor_sync(0xffffffffu, mloc, 1));
        mloc = fmaxf(mloc, __shfl_xor_sync(0xffffffffu, mloc, 2));
        float mnew = fmaxf(m, mloc);
        float alpha = __expf(m - mnew);   // m=-inf, mnew finite -> 0

        __syncthreads();                  // all K reads done before P overwrite
        float psum = 0.f;
#pragma unroll
        for (int j = 0; j < 16; j++) {
            float p = __expf(sreg[j] - mnew);
            KP[r * 65 + qd * 16 + j] = p;
            psum += p;
        }
        psum += __shfl_xor_sync(0xffffffffu, psum, 1);
        psum += __shfl_xor_sync(0xffffffffu, psum, 2);
        l = l * alpha + psum;
#pragma unroll
        for (int i = 0; i < 16; i++) acc[i] *= alpha;
        m = mnew;
        __syncthreads();                  // P fully written

        // O += P @ V
#pragma unroll 4
        for (int j = 0; j < 64; j++) {
            float p = KP[r * 65 + j];
#pragma unroll
            for (int i = 0; i < 16; i++)
                acc[i] += p * Vs[j * 65 + qd * 16 + i];
        }
    }

    float inv_l = 1.0f / l;
    float* Ob = O + (rowbase * D_MODEL) + h * DK;
#pragma unroll
    for (int i = 0; i < 16; i++)
        Ob[(size_t)(qrow0 + r) * D_MODEL + qd * 16 + i] = acc[i] * inv_l;
}

// ---------------------------------------------------------------------------
extern "C" void kernel_launch(void* const* d_in, const int* in_sizes, int n_in,
                              void* d_out, int out_size) {
    const float* x  = (const float*)d_in[0];
    const float* Wq = (const float*)d_in[1];
    const float* Wk = (const float*)d_in[2];
    const float* Wv = (const float*)d_in[3];
    const float* Wo = (const float*)d_in[4];
    float* out = (float*)d_out;

    float *qb, *kb, *vb, *ab;
    cudaGetSymbolAddress((void**)&qb, g_Q);
    cudaGetSymbolAddress((void**)&kb, g_K);
    cudaGetSymbolAddress((void**)&vb, g_V);
    cudaGetSymbolAddress((void**)&ab, g_A);

    dim3 gthreads(16, 16);
    dim3 ggrid(D_MODEL / 64, M_ROWS / 64);   // (16, 64)

    gemm_xwt<<<ggrid, gthreads>>>(x, Wq, qb, M_ROWS, D_MODEL, D_MODEL);
    gemm_xwt<<<ggrid, gthreads>>>(x, Wk, kb, M_ROWS, D_MODEL, D_MODEL);
    gemm_xwt<<<ggrid, gthreads>>>(x, Wv, vb, M_ROWS, D_MODEL, D_MODEL);

    int npairs = M_ROWS * (D_MODEL / 2);
    rope_kernel<<<(npairs + 255) / 256, 256>>>(qb, kb);

    size_t attn_smem = ATTN_SMEM_FLOATS * sizeof(float);  // 49664 B
    cudaFuncSetAttribute(attn_kernel, cudaFuncAttributeMaxDynamicSharedMemorySize,
                         (int)attn_smem);

    dim3 agrid(SEQ / 64, NH, BATCH);          // (32, 16, 2)
    attn_kernel<<<agrid, 256, attn_smem>>>(qb, kb, vb, ab);

    gemm_xwt<<<ggrid, gthreads>>>(ab, Wo, out, M_ROWS, D_MODEL, D_MODEL);
}

// round 7
// speedup vs baseline: 1.4496x; 1.4496x over previous
#include <cuda_runtime.h>
#include <cuda_bf16.h>
#include <cstdint>
#include <math.h>

typedef unsigned int u32;

#define D_MODEL 1024
#define NH 16
#define DK 64
#define BATCH 2
#define SEQ 2048
#define M_ROWS (BATCH * SEQ)   // 4096

#define NEG_INF (__int_as_float(0xff800000))

// Scratch (allocation-free rule: __device__ globals)
__device__ float g_Q[M_ROWS * D_MODEL];
__device__ float g_K[M_ROWS * D_MODEL];
__device__ float g_V[M_ROWS * D_MODEL];
__device__ float g_A[M_ROWS * D_MODEL];

__device__ __nv_bfloat16 g_xhi[M_ROWS * D_MODEL];
__device__ __nv_bfloat16 g_xlo[M_ROWS * D_MODEL];
__device__ __nv_bfloat16 g_ahi[M_ROWS * D_MODEL];
__device__ __nv_bfloat16 g_alo[M_ROWS * D_MODEL];
__device__ __nv_bfloat16 g_whi[4ull * D_MODEL * D_MODEL];
__device__ __nv_bfloat16 g_wlo[4ull * D_MODEL * D_MODEL];

// ---------------------------------------------------------------------------
// Split fp32 -> (hi, lo) bf16 pair. hi+lo carries ~17 mantissa bits.
// ---------------------------------------------------------------------------
__global__ void split_bf16(const float* __restrict__ in,
                           __nv_bfloat16* __restrict__ hi,
                           __nv_bfloat16* __restrict__ lo, int n4)
{
    int i = blockIdx.x * blockDim.x + threadIdx.x;
    if (i >= n4) return;
    float4 v = ((const float4*)in)[i];
    float f0 = v.x, f1 = v.y, f2 = v.z, f3 = v.w;
    __nv_bfloat16 h0 = __float2bfloat16(f0);
    __nv_bfloat16 h1 = __float2bfloat16(f1);
    __nv_bfloat16 h2 = __float2bfloat16(f2);
    __nv_bfloat16 h3 = __float2bfloat16(f3);
    __nv_bfloat16 l0 = __float2bfloat16(f0 - __bfloat162float(h0));
    __nv_bfloat16 l1 = __float2bfloat16(f1 - __bfloat162float(h1));
    __nv_bfloat16 l2 = __float2bfloat16(f2 - __bfloat162float(h2));
    __nv_bfloat16 l3 = __float2bfloat16(f3 - __bfloat162float(h3));
    __nv_bfloat162* hp = (__nv_bfloat162*)(hi + 4 * (size_t)i);
    __nv_bfloat162* lp = (__nv_bfloat162*)(lo + 4 * (size_t)i);
    hp[0] = __halves2bfloat162(h0, h1);
    hp[1] = __halves2bfloat162(h2, h3);
    lp[0] = __halves2bfloat162(l0, l1);
    lp[1] = __halves2bfloat162(l2, l3);
}

// ---------------------------------------------------------------------------
// Tensor-core GEMM: C[M,N] = A[M,K] * B[N,K]^T, fp32 out.
// A,B given as (hi,lo) bf16 splits; 3 mma passes: hi*hi + hi*lo + lo*hi.
// 128x128 tile, BK=32, 8 warps (2m x 4n), warp tile 64x32 (m16n8k16).
// ---------------------------------------------------------------------------
#define BM 128
#define BN 128
#define BKT 32
#define LDT 40   // BKT + 8 bf16 pad (16B) keeps ldmatrix rows 16B-aligned

__device__ __forceinline__ void ldsm_x4(u32* r, const __nv_bfloat16* p)
{
    u32 a = (u32)__cvta_generic_to_shared(p);
    asm volatile("ldmatrix.sync.aligned.m8n8.x4.shared.b16 {%0,%1,%2,%3}, [%4];"
        : "=r"(r[0]), "=r"(r[1]), "=r"(r[2]), "=r"(r[3]) : "r"(a));
}

__device__ __forceinline__ void ldsm_x2(u32* r, const __nv_bfloat16* p)
{
    u32 a = (u32)__cvta_generic_to_shared(p);
    asm volatile("ldmatrix.sync.aligned.m8n8.x2.shared.b16 {%0,%1}, [%2];"
        : "=r"(r[0]), "=r"(r[1]) : "r"(a));
}

__device__ __forceinline__ void mma16816(float* d, const u32* a, const u32* b)
{
    asm volatile("mma.sync.aligned.m16n8k16.row.col.f32.bf16.bf16.f32 "
        "{%0,%1,%2,%3}, {%4,%5,%6,%7}, {%8,%9}, {%0,%1,%2,%3};"
        : "+f"(d[0]), "+f"(d[1]), "+f"(d[2]), "+f"(d[3])
        : "r"(a[0]), "r"(a[1]), "r"(a[2]), "r"(a[3]), "r"(b[0]), "r"(b[1]));
}

__global__ void __launch_bounds__(256) gemm_mma_split(
    const __nv_bfloat16* __restrict__ Ahi, const __nv_bfloat16* __restrict__ Alo,
    const __nv_bfloat16* __restrict__ Bhi, const __nv_bfloat16* __restrict__ Blo,
    float* __restrict__ C, int M, int N, int K)
{
    __shared__ __align__(16) __nv_bfloat16 sAhi[BM][LDT];
    __shared__ __align__(16) __nv_bfloat16 sAlo[BM][LDT];
    __shared__ __align__(16) __nv_bfloat16 sBhi[BN][LDT];
    __shared__ __align__(16) __nv_bfloat16 sBlo[BN][LDT];

    const int tid  = threadIdx.x;
    const int lane = tid & 31;
    const int warp = tid >> 5;
    const int m0 = blockIdx.y * BM;
    const int n0 = blockIdx.x * BN;
    const int wm = (warp & 1) * 64;
    const int wn = (warp >> 1) * 32;

    float acc[4][4][4];
#pragma unroll
    for (int mt = 0; mt < 4; mt++) {
#pragma unroll
        for (int nt = 0; nt < 4; nt++) {
#pragma unroll
            for (int q = 0; q < 4; q++) {
                acc[mt][nt][q] = 0.f;
            }
        }
    }

    for (int k0 = 0; k0 < K; k0 += BKT) {
#pragma unroll
        for (int p = 0; p < 2; p++) {
            int idx = tid + p * 256;
            int r = idx >> 2;
            int c = (idx & 3) * 8;
            *(uint4*)&sAhi[r][c] = *(const uint4*)&Ahi[(size_t)(m0 + r) * K + k0 + c];
            *(uint4*)&sAlo[r][c] = *(const uint4*)&Alo[(size_t)(m0 + r) * K + k0 + c];
            *(uint4*)&sBhi[r][c] = *(const uint4*)&Bhi[(size_t)(n0 + r) * K + k0 + c];
            *(uint4*)&sBlo[r][c] = *(const uint4*)&Blo[(size_t)(n0 + r) * K + k0 + c];
        }
        __syncthreads();

#pragma unroll
        for (int ks = 0; ks < 2; ks++) {
            const int kk = ks * 16;
            u32 ah[4][4];
            u32 al[4][4];
            u32 bh[4][2];
            u32 bl[4][2];
#pragma unroll
            for (int mt = 0; mt < 4; mt++) {
                const int rr = wm + mt * 16 + (lane & 15);
                const int cc = kk + (lane >> 4) * 8;
                ldsm_x4(ah[mt], &sAhi[rr][cc]);
                ldsm_x4(al[mt], &sAlo[rr][cc]);
            }
#pragma unroll
            for (int nt = 0; nt < 4; nt++) {
                const int rr = wn + nt * 8 + (lane & 7);
                const int cc = kk + ((lane >> 3) & 1) * 8;
                ldsm_x2(bh[nt], &sBhi[rr][cc]);
                ldsm_x2(bl[nt], &sBlo[rr][cc]);
            }
#pragma unroll
            for (int mt = 0; mt < 4; mt++) {
#pragma unroll
                for (int nt = 0; nt < 4; nt++) {
                    mma16816(acc[mt][nt], ah[mt], bh[nt]);
                    mma16816(acc[mt][nt], ah[mt], bl[nt]);
                    mma16816(acc[mt][nt], al[mt], bh[nt]);
                }
            }
        }
        __syncthreads();
    }

#pragma unroll
    for (int mt = 0; mt < 4; mt++) {
#pragma unroll
        for (int nt = 0; nt < 4; nt++) {
            const int row = m0 + wm + mt * 16 + (lane >> 2);
            const int col = n0 + wn + nt * 8 + (lane & 3) * 2;
            float2 v0;
            v0.x = acc[mt][nt][0];
            v0.y = acc[mt][nt][1];
            float2 v1;
            v1.x = acc[mt][nt][2];
            v1.y = acc[mt][nt][3];
            *(float2*)&C[(size_t)row * N + col] = v0;
            *(float2*)&C[(size_t)(row + 8) * N + col] = v1;
        }
    }
}

// ---------------------------------------------------------------------------
// RoPE applied in-place to Q and K. Layout [row=b*S+s][h*64+d].
// ---------------------------------------------------------------------------
__global__ void rope_kernel(float* __restrict__ Q, float* __restrict__ K)
{
    int idx = blockIdx.x * blockDim.x + threadIdx.x;
    if (idx >= M_ROWS * (D_MODEL / 2)) return;
    int row = idx >> 9;
    int p   = idx & 511;
    int h = p >> 5;
    int i = p & 31;
    int s = row & (SEQ - 1);

    float freq = powf(10000.0f, -((float)(2 * i) / (float)DK));
    float ang = (float)s * freq;
    float c = cosf(ang), sn = sinf(ang);

    size_t off = (size_t)row * D_MODEL + h * DK + 2 * i;
    float q1 = Q[off], q2 = Q[off + 1];
    Q[off]     = q1 * c - q2 * sn;
    Q[off + 1] = q1 * sn + q2 * c;
    float k1 = K[off], k2 = K[off + 1];
    K[off]     = k1 * c - k2 * sn;
    K[off + 1] = k1 * sn + k2 * c;
}

// ---------------------------------------------------------------------------
// Causal flash attention (fp32 scalar, unchanged this round).
// ---------------------------------------------------------------------------
#define ATTN_SMEM_FLOATS (64 * 64 + 2 * 64 * 65)

__global__ void attn_kernel(const float* __restrict__ Q,
                            const float* __restrict__ K,
                            const float* __restrict__ V,
                            float* __restrict__ O)
{
    extern __shared__ float smem[];
    float* Qt = smem;                 // [64][64]  Qt[kk*64 + r]
    float* KP = smem + 64 * 64;       // [64][65]
    float* Vs = KP + 64 * 65;         // [64][65]

    const int qt = blockIdx.x;
    const int h  = blockIdx.y;
    const int b  = blockIdx.z;
    const int t  = threadIdx.x;
    const int r  = t >> 2;
    const int qd = t & 3;

    const size_t rowbase = (size_t)b * SEQ;
    const float* Qb = Q + (rowbase * D_MODEL) + h * DK;
    const float* Kb = K + (rowbase * D_MODEL) + h * DK;
    const float* Vb = V + (rowbase * D_MODEL) + h * DK;

    const int qrow0 = qt * 64;

    for (int i = t; i < 64 * 64; i += 256) {
        int rr = i >> 6, cc = i & 63;
        Qt[cc * 64 + rr] = Qb[(size_t)(qrow0 + rr) * D_MODEL + cc];
    }

    float m = NEG_INF;
    float l = 0.f;
    float acc[16];
#pragma unroll
    for (int i = 0; i < 16; i++) acc[i] = 0.f;
    const float scale = 0.125f;

    for (int jt = 0; jt <= qt; jt++) {
        const int krow0 = jt * 64;
        __syncthreads();
        for (int i = t; i < 64 * 64; i += 256) {
            int rr = i >> 6, cc = i & 63;
            KP[rr * 65 + cc] = Kb[(size_t)(krow0 + rr) * D_MODEL + cc];
            Vs[rr * 65 + cc] = Vb[(size_t)(krow0 + rr) * D_MODEL + cc];
        }
        __syncthreads();

        float sreg[16];
        float mloc = NEG_INF;
        const bool diag = (jt == qt);
#pragma unroll
        for (int j = 0; j < 16; j++) {
            int c = qd * 16 + j;
            float a2 = 0.f;
#pragma unroll
            for (int kk = 0; kk < 64; kk++)
                a2 += Qt[kk * 64 + r] * KP[c * 65 + kk];
            a2 *= scale;
            if (diag && c > r) a2 = NEG_INF;
            sreg[j] = a2;
            mloc = fmaxf(mloc, a2);
        }
        mloc = fmaxf(mloc, __shfl_xor_sync(0xffffffffu, mloc, 1));
        mloc = fmaxf(mloc, __shfl_xor_sync(0xffffffffu, mloc, 2));
        float mnew = fmaxf(m, mloc);
        float alpha = __expf(m - mnew);

        __syncthreads();
        float psum = 0.f;
#pragma unroll
        for (int j = 0; j < 16; j++) {
            float p = __expf(sreg[j] - mnew);
            KP[r * 65 + qd * 16 + j] = p;
            psum += p;
        }
        psum += __shfl_xor_sync(0xffffffffu, psum, 1);
        psum += __shfl_xor_sync(0xffffffffu, psum, 2);
        l = l * alpha + psum;
#pragma unroll
        for (int i = 0; i < 16; i++) acc[i] *= alpha;
        m = mnew;
        __syncthreads();

#pragma unroll 4
        for (int j = 0; j < 64; j++) {
            float p = KP[r * 65 + j];
#pragma unroll
            for (int i = 0; i < 16; i++)
                acc[i] += p * Vs[j * 65 + qd * 16 + i];
        }
    }

    float inv_l = 1.0f / l;
    float* Ob = O + (rowbase * D_MODEL) + h * DK;
#pragma unroll
    for (int i = 0; i < 16; i++)
        Ob[(size_t)(qrow0 + r) * D_MODEL + qd * 16 + i] = acc[i] * inv_l;
}

// ---------------------------------------------------------------------------
extern "C" void kernel_launch(void* const* d_in, const int* in_sizes, int n_in,
                              void* d_out, int out_size)
{
    const float* x  = (const float*)d_in[0];
    const float* Wq = (const float*)d_in[1];
    const float* Wk = (const float*)d_in[2];
    const float* Wv = (const float*)d_in[3];
    const float* Wo = (const float*)d_in[4];
    float* out = (float*)d_out;

    float* qb = 0;
    float* kb = 0;
    float* vb = 0;
    float* ab = 0;
    cudaGetSymbolAddress((void**)&qb, g_Q);
    cudaGetSymbolAddress((void**)&kb, g_K);
    cudaGetSymbolAddress((void**)&vb, g_V);
    cudaGetSymbolAddress((void**)&ab, g_A);

    __nv_bfloat16* xhi = 0;
    __nv_bfloat16* xlo = 0;
    __nv_bfloat16* ahi = 0;
    __nv_bfloat16* alo = 0;
    __nv_bfloat16* whi = 0;
    __nv_bfloat16* wlo = 0;
    cudaGetSymbolAddress((void**)&xhi, g_xhi);
    cudaGetSymbolAddress((void**)&xlo, g_xlo);
    cudaGetSymbolAddress((void**)&ahi, g_ahi);
    cudaGetSymbolAddress((void**)&alo, g_alo);
    cudaGetSymbolAddress((void**)&whi, g_whi);
    cudaGetSymbolAddress((void**)&wlo, g_wlo);

    const size_t WSZ = (size_t)D_MODEL * D_MODEL;
    const int wN4 = (int)(WSZ / 4);                 // 262144
    const int xN4 = M_ROWS * D_MODEL / 4;           // 1048576
    const int wBlocks = (wN4 + 255) / 256;
    const int xBlocks = (xN4 + 255) / 256;

    split_bf16<<<wBlocks, 256>>>(Wq, whi + 0 * WSZ, wlo + 0 * WSZ, wN4);
    split_bf16<<<wBlocks, 256>>>(Wk, whi + 1 * WSZ, wlo + 1 * WSZ, wN4);
    split_bf16<<<wBlocks, 256>>>(Wv, whi + 2 * WSZ, wlo + 2 * WSZ, wN4);
    split_bf16<<<wBlocks, 256>>>(Wo, whi + 3 * WSZ, wlo + 3 * WSZ, wN4);
    split_bf16<<<xBlocks, 256>>>(x, xhi, xlo, xN4);

    dim3 gg(D_MODEL / BN, M_ROWS / BM);             // (8, 32)
    gemm_mma_split<<<gg, 256>>>(xhi, xlo, whi + 0 * WSZ, wlo + 0 * WSZ, qb,
                                M_ROWS, D_MODEL, D_MODEL);
    gemm_mma_split<<<gg, 256>>>(xhi, xlo, whi + 1 * WSZ, wlo + 1 * WSZ, kb,
                                M_ROWS, D_MODEL, D_MODEL);
    gemm_mma_split<<<gg, 256>>>(xhi, xlo, whi + 2 * WSZ, wlo + 2 * WSZ, vb,
                                M_ROWS, D_MODEL, D_MODEL);

    int npairs = M_ROWS * (D_MODEL / 2);
    rope_kernel<<<(npairs + 255) / 256, 256>>>(qb, kb);

    size_t attn_smem = ATTN_SMEM_FLOATS * sizeof(float);
    cudaFuncSetAttribute(attn_kernel, cudaFuncAttributeMaxDynamicSharedMemorySize,
                         (int)attn_smem);
    dim3 agrid(SEQ / 64, NH, BATCH);
    attn_kernel<<<agrid, 256, attn_smem>>>(qb, kb, vb, ab);

    split_bf16<<<xBlocks, 256>>>(ab, ahi, alo, xN4);
    gemm_mma_split<<<gg, 256>>>(ahi, alo, whi + 3 * WSZ, wlo + 3 * WSZ, out,
                                M_ROWS, D_MODEL, D_MODEL);
}

// round 8
// speedup vs baseline: 7.0142x; 4.8388x over previous
#include <cuda_runtime.h>
#include <cuda_bf16.h>
#include <cstdint>
#include <math.h>

typedef unsigned int u32;

#define D_MODEL 1024
#define NH 16
#define DK 64
#define BATCH 2
#define SEQ 2048
#define M_ROWS (BATCH * SEQ)   // 4096

#define NEG_INF (__int_as_float(0xff800000))

// ---------------------------------------------------------------------------
// Scratch (__device__ globals; no allocs allowed)
// ---------------------------------------------------------------------------
__device__ float g_QKV[(size_t)M_ROWS * 3 * D_MODEL];         // fused QKV proj out

__device__ __nv_bfloat16 g_xhi[(size_t)M_ROWS * D_MODEL];
__device__ __nv_bfloat16 g_xlo[(size_t)M_ROWS * D_MODEL];
__device__ __nv_bfloat16 g_ahi[(size_t)M_ROWS * D_MODEL];     // attn out (hi)
__device__ __nv_bfloat16 g_alo[(size_t)M_ROWS * D_MODEL];     // attn out (lo)
__device__ __nv_bfloat16 g_whi[4ull * D_MODEL * D_MODEL];     // [Wq;Wk;Wv;Wo]
__device__ __nv_bfloat16 g_wlo[4ull * D_MODEL * D_MODEL];

// head-major [b*NH+h][s][dk] bf16 attention operands
#define HM_ELEMS ((size_t)BATCH * NH * SEQ * DK)
__device__ __nv_bfloat16 g_qh[HM_ELEMS];
__device__ __nv_bfloat16 g_ql[HM_ELEMS];
__device__ __nv_bfloat16 g_kh[HM_ELEMS];
__device__ __nv_bfloat16 g_kl[HM_ELEMS];
__device__ __nv_bfloat16 g_vh[HM_ELEMS];
__device__ __nv_bfloat16 g_vl[HM_ELEMS];

// ---------------------------------------------------------------------------
// helpers
// ---------------------------------------------------------------------------
__device__ __forceinline__ void split2(float a, float b,
                                       __nv_bfloat162* hp, __nv_bfloat162* lp)
{
    __nv_bfloat162 h = __floats2bfloat162_rn(a, b);
    float2 hf = __bfloat1622float2(h);
    *hp = h;
    *lp = __floats2bfloat162_rn(a - hf.x, b - hf.y);
}

__device__ __forceinline__ void ldsm_x4(u32* r, const __nv_bfloat16* p)
{
    u32 a = (u32)__cvta_generic_to_shared(p);
    asm volatile("ldmatrix.sync.aligned.m8n8.x4.shared.b16 {%0,%1,%2,%3}, [%4];"
        : "=r"(r[0]), "=r"(r[1]), "=r"(r[2]), "=r"(r[3]) : "r"(a));
}

__device__ __forceinline__ void ldsm_x2(u32* r, const __nv_bfloat16* p)
{
    u32 a = (u32)__cvta_generic_to_shared(p);
    asm volatile("ldmatrix.sync.aligned.m8n8.x2.shared.b16 {%0,%1}, [%2];"
        : "=r"(r[0]), "=r"(r[1]) : "r"(a));
}

__device__ __forceinline__ void ldsm_x2t(u32* r, const __nv_bfloat16* p)
{
    u32 a = (u32)__cvta_generic_to_shared(p);
    asm volatile("ldmatrix.sync.aligned.m8n8.x2.trans.shared.b16 {%0,%1}, [%2];"
        : "=r"(r[0]), "=r"(r[1]) : "r"(a));
}

__device__ __forceinline__ void mma16816(float* d, const u32* a, const u32* b)
{
    asm volatile("mma.sync.aligned.m16n8k16.row.col.f32.bf16.bf16.f32 "
        "{%0,%1,%2,%3}, {%4,%5,%6,%7}, {%8,%9}, {%0,%1,%2,%3};"
        : "+f"(d[0]), "+f"(d[1]), "+f"(d[2]), "+f"(d[3])
        : "r"(a[0]), "r"(a[1]), "r"(a[2]), "r"(a[3]), "r"(b[0]), "r"(b[1]));
}

// ---------------------------------------------------------------------------
// Split fp32 -> (hi, lo) bf16 pair.
// ---------------------------------------------------------------------------
__global__ void split_bf16(const float* __restrict__ in,
                           __nv_bfloat16* __restrict__ hi,
                           __nv_bfloat16* __restrict__ lo, int n4)
{
    int i = blockIdx.x * blockDim.x + threadIdx.x;
    if (i >= n4) return;
    float4 v = ((const float4*)in)[i];
    __nv_bfloat162 h0, l0, h1, l1;
    split2(v.x, v.y, &h0, &l0);
    split2(v.z, v.w, &h1, &l1);
    __nv_bfloat162* hp = (__nv_bfloat162*)(hi + 4 * (size_t)i);
    __nv_bfloat162* lp = (__nv_bfloat162*)(lo + 4 * (size_t)i);
    hp[0] = h0;
    hp[1] = h1;
    lp[0] = l0;
    lp[1] = l1;
}

// ---------------------------------------------------------------------------
// Tensor-core GEMM: C[M,N] = A[M,K] * B[N,K]^T, fp32 out, 3-pass hi/lo split.
// 128x128 tile, BK=32, 8 warps (2m x 4n), warp tile 64x32 (m16n8k16).
// ---------------------------------------------------------------------------
#define BM 128
#define BN 128
#define BKT 32
#define LDT 40

__global__ void __launch_bounds__(256) gemm_mma_split(
    const __nv_bfloat16* __restrict__ Ahi, const __nv_bfloat16* __restrict__ Alo,
    const __nv_bfloat16* __restrict__ Bhi, const __nv_bfloat16* __restrict__ Blo,
    float* __restrict__ C, int M, int N, int K)
{
    __shared__ __align__(16) __nv_bfloat16 sAhi[BM][LDT];
    __shared__ __align__(16) __nv_bfloat16 sAlo[BM][LDT];
    __shared__ __align__(16) __nv_bfloat16 sBhi[BN][LDT];
    __shared__ __align__(16) __nv_bfloat16 sBlo[BN][LDT];

    const int tid  = threadIdx.x;
    const int lane = tid & 31;
    const int warp = tid >> 5;
    const int m0 = blockIdx.y * BM;
    const int n0 = blockIdx.x * BN;
    const int wm = (warp & 1) * 64;
    const int wn = (warp >> 1) * 32;

    float acc[4][4][4];
#pragma unroll
    for (int mt = 0; mt < 4; mt++) {
#pragma unroll
        for (int nt = 0; nt < 4; nt++) {
#pragma unroll
            for (int q = 0; q < 4; q++) {
                acc[mt][nt][q] = 0.f;
            }
        }
    }

    for (int k0 = 0; k0 < K; k0 += BKT) {
#pragma unroll
        for (int p = 0; p < 2; p++) {
            int idx = tid + p * 256;
            int r = idx >> 2;
            int c = (idx & 3) * 8;
            *(uint4*)&sAhi[r][c] = *(const uint4*)&Ahi[(size_t)(m0 + r) * K + k0 + c];
            *(uint4*)&sAlo[r][c] = *(const uint4*)&Alo[(size_t)(m0 + r) * K + k0 + c];
            *(uint4*)&sBhi[r][c] = *(const uint4*)&Bhi[(size_t)(n0 + r) * K + k0 + c];
            *(uint4*)&sBlo[r][c] = *(const uint4*)&Blo[(size_t)(n0 + r) * K + k0 + c];
        }
        __syncthreads();

#pragma unroll
        for (int ks = 0; ks < 2; ks++) {
            const int kk = ks * 16;
            u32 ah[4][4];
            u32 al[4][4];
            u32 bh[4][2];
            u32 bl[4][2];
#pragma unroll
            for (int mt = 0; mt < 4; mt++) {
                const int rr = wm + mt * 16 + (lane & 15);
                const int cc = kk + (lane >> 4) * 8;
                ldsm_x4(ah[mt], &sAhi[rr][cc]);
                ldsm_x4(al[mt], &sAlo[rr][cc]);
            }
#pragma unroll
            for (int nt = 0; nt < 4; nt++) {
                const int rr = wn + nt * 8 + (lane & 7);
                const int cc = kk + ((lane >> 3) & 1) * 8;
                ldsm_x2(bh[nt], &sBhi[rr][cc]);
                ldsm_x2(bl[nt], &sBlo[rr][cc]);
            }
#pragma unroll
            for (int mt = 0; mt < 4; mt++) {
#pragma unroll
                for (int nt = 0; nt < 4; nt++) {
                    mma16816(acc[mt][nt], ah[mt], bh[nt]);
                    mma16816(acc[mt][nt], ah[mt], bl[nt]);
                    mma16816(acc[mt][nt], al[mt], bh[nt]);
                }
            }
        }
        __syncthreads();
    }

#pragma unroll
    for (int mt = 0; mt < 4; mt++) {
#pragma unroll
        for (int nt = 0; nt < 4; nt++) {
            const int row = m0 + wm + mt * 16 + (lane >> 2);
            const int col = n0 + wn + nt * 8 + (lane & 3) * 2;
            float2 v0;
            v0.x = acc[mt][nt][0];
            v0.y = acc[mt][nt][1];
            float2 v1;
            v1.x = acc[mt][nt][2];
            v1.y = acc[mt][nt][3];
            *(float2*)&C[(size_t)row * N + col] = v0;
            *(float2*)&C[(size_t)(row + 8) * N + col] = v1;
        }
    }
}

// ---------------------------------------------------------------------------
// qkv_finish: read fused QKV fp32 [row][3*1024], apply RoPE to Q (x 1/8) and K,
// split all into bf16 hi/lo, write head-major [b*NH+h][s][dk].
// One thread per (row, head, pair).
// ---------------------------------------------------------------------------
__global__ void qkv_finish(const float* __restrict__ QKV,
                           __nv_bfloat16* __restrict__ qh, __nv_bfloat16* __restrict__ ql,
                           __nv_bfloat16* __restrict__ kh, __nv_bfloat16* __restrict__ kl,
                           __nv_bfloat16* __restrict__ vh, __nv_bfloat16* __restrict__ vl)
{
    int idx = blockIdx.x * blockDim.x + threadIdx.x;
    if (idx >= M_ROWS * (D_MODEL / 2)) return;
    int row = idx >> 9;
    int p   = idx & 511;
    int h = p >> 5;
    int i = p & 31;
    int s = row & (SEQ - 1);
    int b = row >> 11;

    float freq = powf(10000.0f, -((float)(2 * i) / (float)DK));
    float ang = (float)s * freq;
    float c = cosf(ang);
    float sn = sinf(ang);

    size_t src = (size_t)row * (3 * D_MODEL) + h * DK + 2 * i;
    float q1 = QKV[src];
    float q2 = QKV[src + 1];
    float k1 = QKV[src + D_MODEL];
    float k2 = QKV[src + D_MODEL + 1];
    float v1 = QKV[src + 2 * D_MODEL];
    float v2 = QKV[src + 2 * D_MODEL + 1];

    float rq1 = (q1 * c - q2 * sn) * 0.125f;   // fold 1/sqrt(dk)
    float rq2 = (q1 * sn + q2 * c) * 0.125f;
    float rk1 = k1 * c - k2 * sn;
    float rk2 = k1 * sn + k2 * c;

    size_t dst = ((size_t)(b * NH + h) * SEQ + s) * DK + 2 * i;
    __nv_bfloat162 h2, l2;
    split2(rq1, rq2, &h2, &l2);
    *(__nv_bfloat162*)&qh[dst] = h2;
    *(__nv_bfloat162*)&ql[dst] = l2;
    split2(rk1, rk2, &h2, &l2);
    *(__nv_bfloat162*)&kh[dst] = h2;
    *(__nv_bfloat162*)&kl[dst] = l2;
    split2(v1, v2, &h2, &l2);
    *(__nv_bfloat162*)&vh[dst] = h2;
    *(__nv_bfloat162*)&vl[dst] = l2;
}

// ---------------------------------------------------------------------------
// MMA flash attention. CTA = 64 q rows x one (h,b). 4 warps, 16 rows each.
// KV streamed 64 at a time. Split-bf16 everywhere (3-pass MMAs).
// Writes output directly as bf16 hi/lo in [row][h*64+d] layout for Wo GEMM.
// ---------------------------------------------------------------------------
__global__ void __launch_bounds__(128) attn_mma(
    const __nv_bfloat16* __restrict__ qh_, const __nv_bfloat16* __restrict__ ql_,
    const __nv_bfloat16* __restrict__ kh_, const __nv_bfloat16* __restrict__ kl_,
    const __nv_bfloat16* __restrict__ vh_, const __nv_bfloat16* __restrict__ vl_,
    __nv_bfloat16* __restrict__ ohi, __nv_bfloat16* __restrict__ olo)
{
    __shared__ __align__(16) __nv_bfloat16 sKh[64][72];
    __shared__ __align__(16) __nv_bfloat16 sKl[64][72];
    __shared__ __align__(16) __nv_bfloat16 sVh[64][72];
    __shared__ __align__(16) __nv_bfloat16 sVl[64][72];

    const int qt = blockIdx.x;
    const int hb = blockIdx.y;            // b*NH + h
    const int t = threadIdx.x;
    const int lane = t & 31;
    const int w = t >> 5;
    const size_t base = (size_t)hb * (SEQ * DK);
    const int q0 = qt * 64;

    // stage Q tile (hi/lo) into K smem, pull into A fragments
    for (int i = t; i < 512; i += 128) {
        int r = i >> 3, c = (i & 7) * 8;
        *(uint4*)&sKh[r][c] = *(const uint4*)&qh_[base + (size_t)(q0 + r) * DK + c];
        *(uint4*)&sKl[r][c] = *(const uint4*)&ql_[base + (size_t)(q0 + r) * DK + c];
    }
    __syncthreads();

    u32 qfh[4][4];
    u32 qfl[4][4];
#pragma unroll
    for (int kc = 0; kc < 4; kc++) {
        const int rr = w * 16 + (lane & 15);
        const int cc = kc * 16 + (lane >> 4) * 8;
        ldsm_x4(qfh[kc], &sKh[rr][cc]);
        ldsm_x4(qfl[kc], &sKl[rr][cc]);
    }

    float m0 = NEG_INF, m1 = NEG_INF, l0 = 0.f, l1 = 0.f;
    float O[8][4];
#pragma unroll
    for (int nt = 0; nt < 8; nt++) {
#pragma unroll
        for (int q = 0; q < 4; q++) O[nt][q] = 0.f;
    }

    for (int jt = 0; jt <= qt; jt++) {
        __syncthreads();       // prior reads of smem done (incl. Q frag extraction)
        const int k0r = jt * 64;
        for (int i = t; i < 512; i += 128) {
            int r = i >> 3, c = (i & 7) * 8;
            size_t g = base + (size_t)(k0r + r) * DK + c;
            *(uint4*)&sKh[r][c] = *(const uint4*)&kh_[g];
            *(uint4*)&sKl[r][c] = *(const uint4*)&kl_[g];
            *(uint4*)&sVh[r][c] = *(const uint4*)&vh_[g];
            *(uint4*)&sVl[r][c] = *(const uint4*)&vl_[g];
        }
        __syncthreads();

        // S = Q @ K^T (3-pass split)
        float S[8][4];
#pragma unroll
        for (int nt = 0; nt < 8; nt++) {
#pragma unroll
            for (int q = 0; q < 4; q++) S[nt][q] = 0.f;
        }
#pragma unroll
        for (int nt = 0; nt < 8; nt++) {
#pragma unroll
            for (int kc = 0; kc < 4; kc++) {
                u32 kbh[2], kbl[2];
                const int rr = nt * 8 + (lane & 7);
                const int cc = kc * 16 + ((lane >> 3) & 1) * 8;
                ldsm_x2(kbh, &sKh[rr][cc]);
                ldsm_x2(kbl, &sKl[rr][cc]);
                mma16816(S[nt], qfh[kc], kbh);
                mma16816(S[nt], qfh[kc], kbl);
                mma16816(S[nt], qfl[kc], kbh);
            }
        }

        // causal mask (diag tile) + row max
        const bool diag = (jt == qt);
        const int rowm = w * 16 + (lane >> 2);
        float tm0 = NEG_INF, tm1 = NEG_INF;
#pragma unroll
        for (int nt = 0; nt < 8; nt++) {
            const int cn = nt * 8 + (lane & 3) * 2;
            if (diag) {
                if (cn > rowm)         S[nt][0] = NEG_INF;
                if (cn + 1 > rowm)     S[nt][1] = NEG_INF;
                if (cn > rowm + 8)     S[nt][2] = NEG_INF;
                if (cn + 1 > rowm + 8) S[nt][3] = NEG_INF;
            }
            tm0 = fmaxf(tm0, fmaxf(S[nt][0], S[nt][1]));
            tm1 = fmaxf(tm1, fmaxf(S[nt][2], S[nt][3]));
        }
        tm0 = fmaxf(tm0, __shfl_xor_sync(0xffffffffu, tm0, 1));
        tm0 = fmaxf(tm0, __shfl_xor_sync(0xffffffffu, tm0, 2));
        tm1 = fmaxf(tm1, __shfl_xor_sync(0xffffffffu, tm1, 1));
        tm1 = fmaxf(tm1, __shfl_xor_sync(0xffffffffu, tm1, 2));

        const float mn0 = fmaxf(m0, tm0);
        const float mn1 = fmaxf(m1, tm1);
        const float a0 = __expf(m0 - mn0);
        const float a1 = __expf(m1 - mn1);

        float ps0 = 0.f, ps1 = 0.f;
#pragma unroll
        for (int nt = 0; nt < 8; nt++) {
            S[nt][0] = __expf(S[nt][0] - mn0);
            S[nt][1] = __expf(S[nt][1] - mn0);
            S[nt][2] = __expf(S[nt][2] - mn1);
            S[nt][3] = __expf(S[nt][3] - mn1);
            ps0 += S[nt][0] + S[nt][1];
            ps1 += S[nt][2] + S[nt][3];
        }
        ps0 += __shfl_xor_sync(0xffffffffu, ps0, 1);
        ps0 += __shfl_xor_sync(0xffffffffu, ps0, 2);
        ps1 += __shfl_xor_sync(0xffffffffu, ps1, 1);
        ps1 += __shfl_xor_sync(0xffffffffu, ps1, 2);
        l0 = l0 * a0 + ps0;
        l1 = l1 * a1 + ps1;
#pragma unroll
        for (int nt = 0; nt < 8; nt++) {
            O[nt][0] *= a0;
            O[nt][1] *= a0;
            O[nt][2] *= a1;
            O[nt][3] *= a1;
        }
        m0 = mn0;
        m1 = mn1;

        // O += P @ V (3-pass split); P fragments built from S registers
#pragma unroll
        for (int kc = 0; kc < 4; kc++) {
            u32 ph[4], pl[4];
            __nv_bfloat162 h2, l2;
            split2(S[2 * kc][0], S[2 * kc][1], &h2, &l2);
            ph[0] = *(u32*)&h2;
            pl[0] = *(u32*)&l2;
            split2(S[2 * kc][2], S[2 * kc][3], &h2, &l2);
            ph[1] = *(u32*)&h2;
            pl[1] = *(u32*)&l2;
            split2(S[2 * kc + 1][0], S[2 * kc + 1][1], &h2, &l2);
            ph[2] = *(u32*)&h2;
            pl[2] = *(u32*)&l2;
            split2(S[2 * kc + 1][2], S[2 * kc + 1][3], &h2, &l2);
            ph[3] = *(u32*)&h2;
            pl[3] = *(u32*)&l2;
#pragma unroll
            for (int nt = 0; nt < 8; nt++) {
                u32 vbh[2], vbl[2];
                const int rr = kc * 16 + (lane & 15);
                ldsm_x2t(vbh, &sVh[rr][nt * 8]);
                ldsm_x2t(vbl, &sVl[rr][nt * 8]);
                mma16816(O[nt], ph, vbh);
                mma16816(O[nt], ph, vbl);
                mma16816(O[nt], pl, vbh);
            }
        }
    }

    // epilogue: normalize, split to bf16 hi/lo, write [row][h*64+d]
    const float i0 = 1.0f / l0;
    const float i1 = 1.0f / l1;
    const int h = hb & (NH - 1);
    const int b = hb >> 4;
    const int s0 = q0 + w * 16 + (lane >> 2);
    const size_t r0 = (size_t)(b * SEQ + s0) * D_MODEL + h * DK + (lane & 3) * 2;
    const size_t r1 = r0 + 8ull * D_MODEL;
#pragma unroll
    for (int nt = 0; nt < 8; nt++) {
        __nv_bfloat162 h2, l2;
        split2(O[nt][0] * i0, O[nt][1] * i0, &h2, &l2);
        *(__nv_bfloat162*)&ohi[r0 + nt * 8] = h2;
        *(__nv_bfloat162*)&olo[r0 + nt * 8] = l2;
        split2(O[nt][2] * i1, O[nt][3] * i1, &h2, &l2);
        *(__nv_bfloat162*)&ohi[r1 + nt * 8] = h2;
        *(__nv_bfloat162*)&olo[r1 + nt * 8] = l2;
    }
}

// ---------------------------------------------------------------------------
extern "C" void kernel_launch(void* const* d_in, const int* in_sizes, int n_in,
                              void* d_out, int out_size)
{
    const float* x  = (const float*)d_in[0];
    const float* Wq = (const float*)d_in[1];
    const float* Wk = (const float*)d_in[2];
    const float* Wv = (const float*)d_in[3];
    const float* Wo = (const float*)d_in[4];
    float* out = (float*)d_out;

    float* qkv = 0;
    cudaGetSymbolAddress((void**)&qkv, g_QKV);

    __nv_bfloat16* xhi = 0;
    __nv_bfloat16* xlo = 0;
    __nv_bfloat16* ahi = 0;
    __nv_bfloat16* alo = 0;
    __nv_bfloat16* whi = 0;
    __nv_bfloat16* wlo = 0;
    cudaGetSymbolAddress((void**)&xhi, g_xhi);
    cudaGetSymbolAddress((void**)&xlo, g_xlo);
    cudaGetSymbolAddress((void**)&ahi, g_ahi);
    cudaGetSymbolAddress((void**)&alo, g_alo);
    cudaGetSymbolAddress((void**)&whi, g_whi);
    cudaGetSymbolAddress((void**)&wlo, g_wlo);

    __nv_bfloat16* qh = 0;
    __nv_bfloat16* ql = 0;
    __nv_bfloat16* kh = 0;
    __nv_bfloat16* kl = 0;
    __nv_bfloat16* vh = 0;
    __nv_bfloat16* vl = 0;
    cudaGetSymbolAddress((void**)&qh, g_qh);
    cudaGetSymbolAddress((void**)&ql, g_ql);
    cudaGetSymbolAddress((void**)&kh, g_kh);
    cudaGetSymbolAddress((void**)&kl, g_kl);
    cudaGetSymbolAddress((void**)&vh, g_vh);
    cudaGetSymbolAddress((void**)&vl, g_vl);

    const size_t WSZ = (size_t)D_MODEL * D_MODEL;
    const int wN4 = (int)(WSZ / 4);
    const int xN4 = M_ROWS * D_MODEL / 4;
    const int wBlocks = (wN4 + 255) / 256;
    const int xBlocks = (xN4 + 255) / 256;

    split_bf16<<<wBlocks, 256>>>(Wq, whi + 0 * WSZ, wlo + 0 * WSZ, wN4);
    split_bf16<<<wBlocks, 256>>>(Wk, whi + 1 * WSZ, wlo + 1 * WSZ, wN4);
    split_bf16<<<wBlocks, 256>>>(Wv, whi + 2 * WSZ, wlo + 2 * WSZ, wN4);
    split_bf16<<<wBlocks, 256>>>(Wo, whi + 3 * WSZ, wlo + 3 * WSZ, wN4);
    split_bf16<<<xBlocks, 256>>>(x, xhi, xlo, xN4);

    // fused QKV projection: C[4096][3072] = x @ [Wq;Wk;Wv]^T
    dim3 gqkv(3 * D_MODEL / BN, M_ROWS / BM);       // (24, 32)
    gemm_mma_split<<<gqkv, 256>>>(xhi, xlo, whi, wlo, qkv,
                                  M_ROWS, 3 * D_MODEL, D_MODEL);

    // RoPE + split + head-major relayout
    int npairs = M_ROWS * (D_MODEL / 2);
    qkv_finish<<<(npairs + 255) / 256, 256>>>(qkv, qh, ql, kh, kl, vh, vl);

    // flash attention (tensor cores)
    dim3 agrid(SEQ / 64, NH * BATCH);               // (32, 32)
    attn_mma<<<agrid, 128>>>(qh, ql, kh, kl, vh, vl, ahi, alo);

    // output projection
    dim3 go(D_MODEL / BN, M_ROWS / BM);             // (8, 32)
    gemm_mma_split<<<go, 256>>>(ahi, alo, whi + 3 * WSZ, wlo + 3 * WSZ, out,
                                M_ROWS, D_MODEL, D_MODEL);
}